// round 11
// baseline (speedup 1.0000x reference)
#include <cuda_runtime.h>
#include <cuda_bf16.h>
#include <math.h>
#include <stdint.h>

#define F    128
#define R    4
#define H    4
#define HC   512
#define DE   16
#define DR   8
#define DW   24   // De + Dr
#define FFNW 256
#define MAXN 40000
#define MAXE 150000
#define NCOL 4096  // 2 * R * HC  (XL cols 0..2047, XR cols 2048..4095)
#define PADK 136   // padded bf16 row length in smem

// ---------------- scratch (static device memory; no allocs allowed) ----------------
__device__ float g_XL[(size_t)MAXN * 2048];
__device__ float g_XR[(size_t)MAXN * 2048];
__device__ float g_HREL[(size_t)MAXN * R * 128];
__device__ float g_EXPS[(size_t)MAXE * H];
__device__ float g_DENOM[(size_t)MAXN * R * H];
__device__ __nv_bfloat16 g_AH[(size_t)MAXN * F];
__device__ __nv_bfloat16 g_AL[(size_t)MAXN * F];
__device__ __nv_bfloat16 g_BH[(size_t)NCOL * F];   // transposed weights [ncol][k]
__device__ __nv_bfloat16 g_BL[(size_t)NCOL * F];
__device__ int g_CNT[R];
__device__ int g_BASE[R + 1];
__device__ int g_CUR[R];
__device__ int g_EPERM[MAXE];

__device__ __forceinline__ uint32_t smem_to_u32(const void* p) {
    uint32_t a;
    asm("{ .reg .u64 t; cvta.to.shared.u64 t, %1; cvt.u32.u64 %0, t; }" : "=r"(a) : "l"(p));
    return a;
}
__device__ __forceinline__ void cp16(uint32_t dst, const void* src) {
    asm volatile("cp.async.cg.shared.global [%0], [%1], 16;" :: "r"(dst), "l"(src));
}
__device__ __forceinline__ void cp16z(uint32_t dst, const void* src, int sz) {
    asm volatile("cp.async.cg.shared.global [%0], [%1], 16, %2;" :: "r"(dst), "l"(src), "r"(sz));
}
#define CP_COMMIT() asm volatile("cp.async.commit_group;" ::: "memory")

// ---------------- prep: fp32 -> bf16 hi/lo split ----------------
__global__ void prep_a_kernel(const float* __restrict__ h, int Nn) {
    int i = blockIdx.x * blockDim.x + threadIdx.x;
    if (i >= Nn * F) return;
    float v = h[i];
    __nv_bfloat16 hi = __float2bfloat16(v);
    g_AH[i] = hi;
    g_AL[i] = __float2bfloat16(v - __bfloat162float(hi));
}
__global__ void prep_w_kernel(const float* __restrict__ Wl, const float* __restrict__ Wr) {
    int i = blockIdx.x * blockDim.x + threadIdx.x;
    if (i >= NCOL * F) return;
    int j = i >> 7, k = i & 127;
    float w;
    if (j < 2048) w = Wl[(size_t)((j >> 9) * F + k) * HC + (j & 511)];
    else { int j2 = j - 2048; w = Wr[(size_t)((j2 >> 9) * F + k) * HC + (j2 & 511)]; }
    __nv_bfloat16 hi = __float2bfloat16(w);
    g_BH[i] = hi;
    g_BL[i] = __float2bfloat16(w - __bfloat162float(hi));
}

// ---------------- init ----------------
__global__ void init_kernel(int N) {
    if (blockIdx.x == 0 && threadIdx.x < R) { g_CNT[threadIdx.x] = 0; g_CUR[threadIdx.x] = 0; }
    size_t total4 = (size_t)N * R * 32;   // HREL as float4
    size_t small = (size_t)N * R * H;
    float4 z = make_float4(0.f, 0.f, 0.f, 0.f);
    for (size_t i = (size_t)blockIdx.x * blockDim.x + threadIdx.x; i < total4;
         i += (size_t)gridDim.x * blockDim.x) {
        ((float4*)g_HREL)[i] = z;
        if (i < small) g_DENOM[i] = 0.f;
    }
}

// ---------------- projection GEMM via mma.sync bf16 (hi/lo split, fp32 acc) ------
// 512 threads / 16 warps, 4x4 warp grid, warp tile 32m x 32n. C tile 128x128.
__global__ __launch_bounds__(512, 1) void proj_hmma_kernel(
    const float* __restrict__ bl, const float* __restrict__ br, int Nn)
{
    extern __shared__ char smem[];
    __nv_bfloat16* Ah = (__nv_bfloat16*)smem;          // [128][PADK]
    __nv_bfloat16* Al = Ah + 128 * PADK;
    __nv_bfloat16* Bbuf0 = Al + 128 * PADK;            // hi then lo, 2*128*PADK
    __nv_bfloat16* Bbuf1 = Bbuf0 + 2 * 128 * PADK;

    int tid = threadIdx.x, wid = tid >> 5, lane = tid & 31;
    int m0 = blockIdx.x * 128;
    int jt0 = blockIdx.y * 4;
    int wm = (wid & 3) * 32;
    int wn = (wid >> 2) * 32;
    int g = lane >> 3, rr8 = lane & 7;

    {
        uint32_t dA = smem_to_u32(Ah);
        uint32_t dAl = smem_to_u32(Al);
        const uint4* ah = (const uint4*)g_AH;
        const uint4* al = (const uint4*)g_AL;
        for (int i = tid; i < 2048; i += 512) {
            int row = i >> 4, q = i & 15;
            int gm = m0 + row;
            int sz = (gm < Nn) ? 16 : 0;
            size_t gi = (size_t)((gm < Nn) ? gm : 0) * 16 + q;
            uint32_t off = (uint32_t)(row * PADK + q * 8) * 2;
            cp16z(dA + off, ah + gi, sz);
            cp16z(dAl + off, al + gi, sz);
        }
        uint32_t dB = smem_to_u32(Bbuf0);
        const uint4* bh = (const uint4*)g_BH;
        const uint4* blo = (const uint4*)g_BL;
        for (int i = tid; i < 2048; i += 512) {
            int row = i >> 4, q = i & 15;
            size_t gr = (size_t)(jt0 * 128 + row) * 16 + q;
            uint32_t off = (uint32_t)(row * PADK + q * 8) * 2;
            cp16(dB + off, bh + gr);
            cp16(dB + 2u * 128 * PADK + off, blo + gr);
        }
        CP_COMMIT();
    }

    for (int t = 0; t < 4; ++t) {
        __nv_bfloat16* cur = (t & 1) ? Bbuf1 : Bbuf0;
        if (t < 3) {
            __nv_bfloat16* nxt = (t & 1) ? Bbuf0 : Bbuf1;
            uint32_t dB = smem_to_u32(nxt);
            const uint4* bh = (const uint4*)g_BH;
            const uint4* blo = (const uint4*)g_BL;
            int jtn = jt0 + t + 1;
            for (int i = tid; i < 2048; i += 512) {
                int row = i >> 4, q = i & 15;
                size_t gr = (size_t)(jtn * 128 + row) * 16 + q;
                uint32_t off = (uint32_t)(row * PADK + q * 8) * 2;
                cp16(dB + off, bh + gr);
                cp16(dB + 2u * 128 * PADK + off, blo + gr);
            }
            CP_COMMIT();
            asm volatile("cp.async.wait_group 1;" ::: "memory");
        } else {
            asm volatile("cp.async.wait_group 0;" ::: "memory");
        }
        __syncthreads();

        float c[2][4][4];
#pragma unroll
        for (int mi = 0; mi < 2; mi++)
#pragma unroll
            for (int q = 0; q < 4; q++)
#pragma unroll
                for (int v = 0; v < 4; v++) c[mi][q][v] = 0.f;

#pragma unroll
        for (int p = 0; p < 3; ++p) {
            const __nv_bfloat16* As = (p == 2) ? Al : Ah;
            const __nv_bfloat16* Bs = (p == 1) ? (cur + 2 * 64 * PADK) : cur;
            uint32_t ab = smem_to_u32(As);
            uint32_t bbs = smem_to_u32(Bs);
#pragma unroll
            for (int k0 = 0; k0 < 128; k0 += 16) {
                uint32_t a[2][4];
#pragma unroll
                for (int mi = 0; mi < 2; mi++) {
                    uint32_t addr = ab + (uint32_t)(((wm + mi * 16 + (g & 1) * 8 + rr8) * PADK
                                                     + (g >> 1) * 8 + k0) * 2);
                    asm volatile("ldmatrix.sync.aligned.m8n8.x4.shared.b16 {%0,%1,%2,%3}, [%4];"
                        : "=r"(a[mi][0]), "=r"(a[mi][1]), "=r"(a[mi][2]), "=r"(a[mi][3])
                        : "r"(addr));
                }
                uint32_t b[4][2];
#pragma unroll
                for (int q = 0; q < 2; q++) {
                    uint32_t addr = bbs + (uint32_t)(((wn + q * 16 + (g >> 1) * 8 + rr8) * PADK
                                                      + (g & 1) * 8 + k0) * 2);
                    uint32_t r0, r1, r2, r3;
                    asm volatile("ldmatrix.sync.aligned.m8n8.x4.shared.b16 {%0,%1,%2,%3}, [%4];"
                        : "=r"(r0), "=r"(r1), "=r"(r2), "=r"(r3) : "r"(addr));
                    b[2 * q][0] = r0; b[2 * q][1] = r1;
                    b[2 * q + 1][0] = r2; b[2 * q + 1][1] = r3;
                }
#pragma unroll
                for (int mi = 0; mi < 2; mi++)
#pragma unroll
                    for (int q = 0; q < 4; q++)
                        asm volatile(
                            "mma.sync.aligned.m16n8k16.row.col.f32.bf16.bf16.f32 "
                            "{%0,%1,%2,%3},{%4,%5,%6,%7},{%8,%9},{%0,%1,%2,%3};"
                            : "+f"(c[mi][q][0]), "+f"(c[mi][q][1]),
                              "+f"(c[mi][q][2]), "+f"(c[mi][q][3])
                            : "r"(a[mi][0]), "r"(a[mi][1]), "r"(a[mi][2]), "r"(a[mi][3]),
                              "r"(b[q][0]), "r"(b[q][1]));
            }
        }

        {
            int jt = jt0 + t;
            float* base; const float* bb; int colTile;
            if (jt < 16) { base = g_XL; bb = bl + jt * 128; colTile = jt * 128; }
            else { base = g_XR; bb = br + (jt - 16) * 128; colTile = (jt - 16) * 128; }
            int rrow = lane >> 2, cc2 = (lane & 3) * 2;
#pragma unroll
            for (int mi = 0; mi < 2; mi++) {
                int gm0 = m0 + wm + mi * 16 + rrow;
#pragma unroll
                for (int q = 0; q < 4; q++) {
                    int col = wn + q * 8 + cc2;
                    float b0v = bb[col], b1v = bb[col + 1];
                    if (gm0 < Nn) {
                        float2 v; v.x = c[mi][q][0] + b0v; v.y = c[mi][q][1] + b1v;
                        *(float2*)&base[(size_t)gm0 * 2048 + colTile + col] = v;
                    }
                    if (gm0 + 8 < Nn) {
                        float2 v; v.x = c[mi][q][2] + b0v; v.y = c[mi][q][3] + b1v;
                        *(float2*)&base[(size_t)(gm0 + 8) * 2048 + colTile + col] = v;
                    }
                }
            }
        }
        __syncthreads();
    }
}

// ---------------- edge bucketing by relation (warp-aggregated counting sort) ------
__global__ void hist_kernel(const int* __restrict__ et, int E) {
    int i = blockIdx.x * blockDim.x + threadIdx.x;
    if (i >= E) return;
    int r = et[i];
    unsigned act = __activemask();
    unsigned peers = __match_any_sync(act, r);
    int leader = __ffs(peers) - 1;
    if ((threadIdx.x & 31) == leader) atomicAdd(&g_CNT[r], __popc(peers));
}
__global__ void prefix_kernel() {
    if (threadIdx.x == 0) {
        int s = 0;
        for (int r = 0; r < R; r++) { g_BASE[r] = s; s += g_CNT[r]; }
        g_BASE[R] = s;
    }
}
__global__ void scatter_kernel(const int* __restrict__ et, int E) {
    int i = blockIdx.x * blockDim.x + threadIdx.x;
    if (i >= E) return;
    int lane = threadIdx.x & 31;
    int r = et[i];
    unsigned act = __activemask();
    unsigned peers = __match_any_sync(act, r);
    int leader = __ffs(peers) - 1;
    int rank = __popc(peers & ((1u << lane) - 1u));
    int base = 0;
    if (lane == leader) base = atomicAdd(&g_CUR[r], __popc(peers));
    base = __shfl_sync(act, base, leader);
    g_EPERM[g_BASE[r] + base + rank] = i;
}

// ---------------- edge scores + exp + denom (8 same-relation edges / block) -------
__global__ __launch_bounds__(128) void edge_score_kernel(
    const int* __restrict__ ei, const int* __restrict__ et,
    const float* __restrict__ ea, const float* __restrict__ rel,
    const float* __restrict__ We, const float* __restrict__ att, int E)
{
    int t = threadIdx.x;
    int e0 = blockIdx.x * 8;
    int ne = min(8, E - e0);
    __shared__ int s_e[8], s_src[8], s_dst[8], s_r[8];
    __shared__ float s_sw[8][DW];
    if (t < 8) {
        int k = g_EPERM[(t < ne) ? (e0 + t) : e0];
        s_e[t] = k; s_src[t] = ei[k]; s_dst[t] = ei[E + k]; s_r[t] = et[k];
    }
    __syncthreads();
    for (int i = t; i < 8 * DW; i += 128) {
        int j = i / DW, d = i % DW;
        s_sw[j][d] = (d < DE) ? ea[(size_t)s_e[j] * DE + d] : rel[s_r[j] * DR + (d - DE)];
    }
    __syncthreads();

    int hc = t * 4;
    int head = t >> 5;
    float4 w[DW];
    float4 a4 = make_float4(0.f, 0.f, 0.f, 0.f);
    int rcur = -1;

    for (int j = 0; j < ne; j++) {
        int r = s_r[j];
        if (r != rcur) {
            const float* Wp = We + (size_t)r * DW * HC + hc;
#pragma unroll
            for (int d = 0; d < DW; d++) w[d] = *(const float4*)&Wp[(size_t)d * HC];
            a4 = *(const float4*)&att[r * HC + hc];
            rcur = r;
        }
        float4 xl = __ldcg((const float4*)&g_XL[(size_t)s_src[j] * 2048 + r * 512 + hc]);
        float4 xr = __ldcg((const float4*)&g_XR[(size_t)s_dst[j] * 2048 + r * 512 + hc]);
        float4 ef = make_float4(0.f, 0.f, 0.f, 0.f);
#pragma unroll
        for (int d = 0; d < DW; d++) {
            float s = s_sw[j][d];
            ef.x += s * w[d].x; ef.y += s * w[d].y;
            ef.z += s * w[d].z; ef.w += s * w[d].w;
        }
        float p = 0.f, v;
        v = xl.x + xr.x + ef.x; v = v > 0.f ? v : 0.2f * v; p += v * a4.x;
        v = xl.y + xr.y + ef.y; v = v > 0.f ? v : 0.2f * v; p += v * a4.y;
        v = xl.z + xr.z + ef.z; v = v > 0.f ? v : 0.2f * v; p += v * a4.z;
        v = xl.w + xr.w + ef.w; v = v > 0.f ? v : 0.2f * v; p += v * a4.w;
#pragma unroll
        for (int o = 16; o; o >>= 1) p += __shfl_down_sync(0xffffffffu, p, o);
        if ((t & 31) == 0) {
            // scores are bounded (~|s|<10) -> exp without max subtraction is safe
            float ex = expf(p);
            g_EXPS[(size_t)s_e[j] * H + head] = ex;
            atomicAdd(&g_DENOM[((size_t)s_dst[j] * R + r) * H + head], ex);
        }
    }
}

// ---------------- normalize + scatter messages (head-mean folded in) ----------------
__global__ __launch_bounds__(128) void message_kernel(
    const int* __restrict__ ei, const int* __restrict__ et, int E)
{
    int w = threadIdx.x >> 5;
    int lane = threadIdx.x & 31;
    int e = blockIdx.x * 4 + w;
    if (e >= E) return;
    int src = ei[e], dst = ei[E + e], r = et[e];
    size_t segb = ((size_t)dst * R + r) * H;
    float al[4];
#pragma unroll
    for (int k = 0; k < 4; k++) al[k] = g_EXPS[(size_t)e * H + k] / g_DENOM[segb + k];
    int c = lane * 4;
    const float* xp = &g_XL[(size_t)src * 2048 + r * 512];
    float4 acc = make_float4(0.f, 0.f, 0.f, 0.f);
#pragma unroll
    for (int k = 0; k < 4; k++) {
        float4 x = __ldcg((const float4*)&xp[k * 128 + c]);
        acc.x += al[k] * x.x; acc.y += al[k] * x.y;
        acc.z += al[k] * x.z; acc.w += al[k] * x.w;
    }
    float* hb = &g_HREL[((size_t)dst * R + r) * 128 + c];
    atomicAdd(&hb[0], 0.25f * acc.x);
    atomicAdd(&hb[1], 0.25f * acc.y);
    atomicAdd(&hb[2], 0.25f * acc.z);
    atomicAdd(&hb[3], 0.25f * acc.w);
}

// ---------------- gated fusion + LN1 + FFN (f32x2) + LN2 : 32 nodes / block -------
#define H1T(f, n) smf[(f) * 34 + (n)]
#define UST(j, n) smf[128 * 34 + (j) * 34 + (n)]
#define PSN(n, c) smf[128 * 34 + 256 * 34 + (n) * 128 + (c)]
#define NODE_SMEM ((128 * 34 + 256 * 34 + 32 * 128) * 4)

__global__ __launch_bounds__(256, 2) void node_kernel(
    const float* __restrict__ hin, const float* __restrict__ bias, const float* __restrict__ gate,
    const float* __restrict__ g1, const float* __restrict__ bt1,
    const float* __restrict__ g2, const float* __restrict__ bt2,
    const float* __restrict__ Wf1, const float* __restrict__ bf1,
    const float* __restrict__ Wf2, const float* __restrict__ bf2,
    float* __restrict__ out, int N)
{
    extern __shared__ float smf[];
    int t = threadIdx.x, w = t >> 5, lane = t & 31;
    int nb = blockIdx.x * 32;

    float q0 = gate[0], q1 = gate[1], q2 = gate[2], q3 = gate[3];
    float gm = fmaxf(fmaxf(q0, q1), fmaxf(q2, q3));
    float e0 = expf(q0 - gm), e1 = expf(q1 - gm), e2 = expf(q2 - gm), e3 = expf(q3 - gm);
    float gs = e0 + e1 + e2 + e3;
    float gw0 = e0 / gs, gw1 = e1 / gs, gw2 = e2 / gs, gw3 = e3 / gs;

#pragma unroll
    for (int q = 0; q < 4; q++) {
        int ni = w * 4 + q;
        int n = nb + ni;
        bool valid = n < N;
        const float* hr = g_HREL + (size_t)n * 512;
        const float* hp = hin + (size_t)n * 128;
        float y[4];
        float s = 0.f, s2 = 0.f;
#pragma unroll
        for (int k = 0; k < 4; k++) {
            int c = k * 32 + lane;
            float v = 0.f;
            if (valid) {
                float hm = gw0 * (hr[c] + bias[c])
                         + gw1 * (hr[128 + c] + bias[128 + c])
                         + gw2 * (hr[256 + c] + bias[256 + c])
                         + gw3 * (hr[384 + c] + bias[384 + c]);
                v = hp[c] + hm;
            }
            y[k] = v; s += v; s2 += v * v;
        }
#pragma unroll
        for (int o = 16; o; o >>= 1) {
            s += __shfl_xor_sync(0xffffffffu, s, o);
            s2 += __shfl_xor_sync(0xffffffffu, s2, o);
        }
        float m = s * (1.f / 128.f);
        float rs = rsqrtf(s2 * (1.f / 128.f) - m * m + 1e-5f);
#pragma unroll
        for (int k = 0; k < 4; k++) {
            int c = k * 32 + lane;
            H1T(c, ni) = (y[k] - m) * rs * g1[c] + bt1[c];
        }
    }
    __syncthreads();

    {
        unsigned long long acc[16];
#pragma unroll
        for (int p = 0; p < 16; p++) acc[p] = 0ull;
        for (int f = 0; f < 128; f++) {
            float wv = Wf1[f * FFNW + t];
            unsigned long long wp;
            asm("mov.b64 %0, {%1, %1};" : "=l"(wp) : "f"(wv));
#pragma unroll
            for (int p = 0; p < 16; p++) {
                unsigned long long hp = *(const unsigned long long*)&H1T(f, 2 * p);
                asm("fma.rn.f32x2 %0, %1, %2, %0;" : "+l"(acc[p]) : "l"(hp), "l"(wp));
            }
        }
        float bj = bf1[t];
#pragma unroll
        for (int p = 0; p < 16; p++) {
            float u0, u1;
            asm("mov.b64 {%0, %1}, %2;" : "=f"(u0), "=f"(u1) : "l"(acc[p]));
            u0 += bj; u1 += bj;
            UST(t, 2 * p) = u0 / (1.f + expf(-u0));
            UST(t, 2 * p + 1) = u1 / (1.f + expf(-u1));
        }
    }
    __syncthreads();

    {
        int c = t & 127, half = t >> 7;
        unsigned long long acc[16];
#pragma unroll
        for (int p = 0; p < 16; p++) acc[p] = 0ull;
        for (int jj = 0; jj < 128; jj++) {
            int j = half * 128 + jj;
            float wv = Wf2[j * 128 + c];
            unsigned long long wp;
            asm("mov.b64 %0, {%1, %1};" : "=l"(wp) : "f"(wv));
#pragma unroll
            for (int p = 0; p < 16; p++) {
                unsigned long long up = *(const unsigned long long*)&UST(j, 2 * p);
                asm("fma.rn.f32x2 %0, %1, %2, %0;" : "+l"(acc[p]) : "l"(up), "l"(wp));
            }
        }
        if (half == 0) {
#pragma unroll
            for (int p = 0; p < 16; p++) {
                float v0, v1;
                asm("mov.b64 {%0, %1}, %2;" : "=f"(v0), "=f"(v1) : "l"(acc[p]));
                PSN(2 * p, c) = v0;
                PSN(2 * p + 1, c) = v1;
            }
        }
        __syncthreads();
        if (half == 1) {
            float bc = bf2[c];
#pragma unroll
            for (int p = 0; p < 16; p++) {
                float v0, v1;
                asm("mov.b64 {%0, %1}, %2;" : "=f"(v0), "=f"(v1) : "l"(acc[p]));
                PSN(2 * p, c) += v0 + bc + H1T(c, 2 * p);
                PSN(2 * p + 1, c) += v1 + bc + H1T(c, 2 * p + 1);
            }
        }
    }
    __syncthreads();

#pragma unroll
    for (int q = 0; q < 4; q++) {
        int ni = w * 4 + q;
        int n = nb + ni;
        float v[4];
        float s = 0.f, s2 = 0.f;
#pragma unroll
        for (int k = 0; k < 4; k++) {
            int c = k * 32 + lane;
            float x = PSN(ni, c);
            v[k] = x; s += x; s2 += x * x;
        }
#pragma unroll
        for (int o = 16; o; o >>= 1) {
            s += __shfl_xor_sync(0xffffffffu, s, o);
            s2 += __shfl_xor_sync(0xffffffffu, s2, o);
        }
        float m = s * (1.f / 128.f);
        float rs = rsqrtf(s2 * (1.f / 128.f) - m * m + 1e-5f);
        if (n < N) {
#pragma unroll
            for (int k = 0; k < 4; k++) {
                int c = k * 32 + lane;
                out[(size_t)n * 128 + c] = (v[k] - m) * rs * g2[c] + bt2[c];
            }
        }
    }
}

// ---------------- launcher ----------------
extern "C" void kernel_launch(void* const* d_in, const int* in_sizes, int n_in,
                              void* d_out, int out_size)
{
    const float* h    = (const float*)d_in[0];
    const int*   ei   = (const int*)d_in[1];
    const float* ea   = (const float*)d_in[2];
    const int*   et   = (const int*)d_in[3];
    const float* rel  = (const float*)d_in[4];
    const float* Wl   = (const float*)d_in[5];
    const float* bl   = (const float*)d_in[6];
    const float* Wr   = (const float*)d_in[7];
    const float* br   = (const float*)d_in[8];
    const float* We   = (const float*)d_in[9];
    const float* att  = (const float*)d_in[10];
    const float* bias = (const float*)d_in[11];
    const float* gate = (const float*)d_in[12];
    const float* g1   = (const float*)d_in[13];
    const float* bt1  = (const float*)d_in[14];
    const float* g2   = (const float*)d_in[15];
    const float* bt2  = (const float*)d_in[16];
    const float* Wf1  = (const float*)d_in[17];
    const float* bf1  = (const float*)d_in[18];
    const float* Wf2  = (const float*)d_in[19];
    const float* bf2  = (const float*)d_in[20];

    int N = in_sizes[0] / F;
    int E = in_sizes[3];
    float* out = (float*)d_out;

    const int SMEM_GEMM = 6 * 128 * PADK * 2;  // 208896 bytes
    cudaFuncSetAttribute(proj_hmma_kernel, cudaFuncAttributeMaxDynamicSharedMemorySize, SMEM_GEMM);
    cudaFuncSetAttribute(node_kernel, cudaFuncAttributeMaxDynamicSharedMemorySize, NODE_SMEM);

    // order: proj is the 4th launch so the profiler slot captures it
    prep_a_kernel<<<(N * F + 255) / 256, 256>>>(h, N);
    prep_w_kernel<<<(NCOL * F + 255) / 256, 256>>>(Wl, Wr);
    init_kernel<<<4096, 256>>>(N);

    dim3 gg((N + 127) / 128, 8);
    proj_hmma_kernel<<<gg, 512, SMEM_GEMM>>>(bl, br, N);

    hist_kernel<<<(E + 255) / 256, 256>>>(et, E);
    prefix_kernel<<<1, 32>>>();
    scatter_kernel<<<(E + 255) / 256, 256>>>(et, E);

    edge_score_kernel<<<(E + 7) / 8, 128>>>(ei, et, ea, rel, We, att, E);
    message_kernel<<<(E + 3) / 4, 128>>>(ei, et, E);

    node_kernel<<<(N + 31) / 32, 256, NODE_SMEM>>>(h, bias, gate, g1, bt1, g2, bt2,
                                                   Wf1, bf1, Wf2, bf2, out, N);
}

// round 12
// speedup vs baseline: 1.0925x; 1.0925x over previous
#include <cuda_runtime.h>
#include <cuda_bf16.h>
#include <math.h>
#include <stdint.h>

#define F    128
#define R    4
#define H    4
#define HC   512
#define DE   16
#define DR   8
#define DW   24   // De + Dr
#define FFNW 256
#define MAXN 40000
#define MAXE 150000
#define NCOL 4096  // 2 * R * HC  (XL cols 0..2047, XR cols 2048..4095)
#define PADK 136   // padded bf16 row length in smem

// ---------------- scratch (static device memory; no allocs allowed) ----------------
__device__ float g_XL[(size_t)MAXN * 2048];
__device__ float g_XR[(size_t)MAXN * 2048];
__device__ float g_HREL[(size_t)MAXN * R * 128];
__device__ float g_EXPS[(size_t)MAXE * H];
__device__ float g_DENOM[(size_t)MAXN * R * H];
__device__ __nv_bfloat16 g_AH[(size_t)MAXN * F];
__device__ __nv_bfloat16 g_AL[(size_t)MAXN * F];
__device__ __nv_bfloat16 g_BH[(size_t)NCOL * F];   // transposed weights [ncol][k]
__device__ __nv_bfloat16 g_BL[(size_t)NCOL * F];
__device__ int g_CNT[R];
__device__ int g_BASE[R + 1];
__device__ int g_CUR[R];
__device__ int g_EPERM[MAXE];

__device__ __forceinline__ uint32_t smem_to_u32(const void* p) {
    uint32_t a;
    asm("{ .reg .u64 t; cvta.to.shared.u64 t, %1; cvt.u32.u64 %0, t; }" : "=r"(a) : "l"(p));
    return a;
}
__device__ __forceinline__ void cp16(uint32_t dst, const void* src) {
    asm volatile("cp.async.cg.shared.global [%0], [%1], 16;" :: "r"(dst), "l"(src));
}
__device__ __forceinline__ void cp16z(uint32_t dst, const void* src, int sz) {
    asm volatile("cp.async.cg.shared.global [%0], [%1], 16, %2;" :: "r"(dst), "l"(src), "r"(sz));
}
#define CP_COMMIT() asm volatile("cp.async.commit_group;" ::: "memory")

// ---------------- prep: fp32 -> bf16 hi/lo split ----------------
__global__ void prep_a_kernel(const float* __restrict__ h, int Nn) {
    int i = blockIdx.x * blockDim.x + threadIdx.x;
    if (i >= Nn * F) return;
    float v = h[i];
    __nv_bfloat16 hi = __float2bfloat16(v);
    g_AH[i] = hi;
    g_AL[i] = __float2bfloat16(v - __bfloat162float(hi));
}
__global__ void prep_w_kernel(const float* __restrict__ Wl, const float* __restrict__ Wr) {
    int i = blockIdx.x * blockDim.x + threadIdx.x;
    if (i >= NCOL * F) return;
    int j = i >> 7, k = i & 127;
    float w;
    if (j < 2048) w = Wl[(size_t)((j >> 9) * F + k) * HC + (j & 511)];
    else { int j2 = j - 2048; w = Wr[(size_t)((j2 >> 9) * F + k) * HC + (j2 & 511)]; }
    __nv_bfloat16 hi = __float2bfloat16(w);
    g_BH[i] = hi;
    g_BL[i] = __float2bfloat16(w - __bfloat162float(hi));
}

// ---------------- init ----------------
__global__ void init_kernel(int N) {
    if (blockIdx.x == 0 && threadIdx.x < R) { g_CNT[threadIdx.x] = 0; g_CUR[threadIdx.x] = 0; }
    size_t total4 = (size_t)N * R * 32;   // HREL as float4
    size_t small = (size_t)N * R * H;
    float4 z = make_float4(0.f, 0.f, 0.f, 0.f);
    for (size_t i = (size_t)blockIdx.x * blockDim.x + threadIdx.x; i < total4;
         i += (size_t)gridDim.x * blockDim.x) {
        ((float4*)g_HREL)[i] = z;
        if (i < small) g_DENOM[i] = 0.f;
    }
}

// ---------------- projection GEMM via mma.sync bf16 (hi/lo split, fp32 acc) ------
// 256 threads / 8 warps, 4x2 warp grid, warp tile 32m x 64n. C tile 128x128.
// Flattened (product, k) mainloop with double-buffered register fragments:
// iteration i+1's ldmatrix issues while iteration i's 16 MMAs execute.
__global__ __launch_bounds__(256, 1) void proj_hmma_kernel(
    const float* __restrict__ bl, const float* __restrict__ br, int Nn)
{
    extern __shared__ char smem[];
    __nv_bfloat16* Ah = (__nv_bfloat16*)smem;          // [128][PADK]
    __nv_bfloat16* Al = Ah + 128 * PADK;
    __nv_bfloat16* Bbuf0 = Al + 128 * PADK;            // hi then lo, 2*128*PADK
    __nv_bfloat16* Bbuf1 = Bbuf0 + 2 * 128 * PADK;

    int tid = threadIdx.x, wid = tid >> 5, lane = tid & 31;
    int m0 = blockIdx.x * 128;
    int jt0 = blockIdx.y * 4;
    int wm = (wid & 3) * 32;
    int wn = (wid >> 2) * 64;
    int g = lane >> 3, rr8 = lane & 7;

    // per-warp ldmatrix address bases (byte offsets within a tile)
    uint32_t aBase[2], bBase[4];
#pragma unroll
    for (int mi = 0; mi < 2; mi++)
        aBase[mi] = (uint32_t)(((wm + mi * 16 + (g & 1) * 8 + rr8) * PADK + (g >> 1) * 8) * 2);
#pragma unroll
    for (int q = 0; q < 4; q++)
        bBase[q] = (uint32_t)(((wn + q * 16 + (g >> 1) * 8 + rr8) * PADK + (g & 1) * 8) * 2);

    {
        uint32_t dA = smem_to_u32(Ah);
        uint32_t dAl = smem_to_u32(Al);
        const uint4* ah = (const uint4*)g_AH;
        const uint4* al = (const uint4*)g_AL;
        for (int i = tid; i < 2048; i += 256) {
            int row = i >> 4, q = i & 15;
            int gm = m0 + row;
            int sz = (gm < Nn) ? 16 : 0;
            size_t gi = (size_t)((gm < Nn) ? gm : 0) * 16 + q;
            uint32_t off = (uint32_t)(row * PADK + q * 8) * 2;
            cp16z(dA + off, ah + gi, sz);
            cp16z(dAl + off, al + gi, sz);
        }
        uint32_t dB = smem_to_u32(Bbuf0);
        const uint4* bh = (const uint4*)g_BH;
        const uint4* blo = (const uint4*)g_BL;
        for (int i = tid; i < 2048; i += 256) {
            int row = i >> 4, q = i & 15;
            size_t gr = (size_t)(jt0 * 128 + row) * 16 + q;
            uint32_t off = (uint32_t)(row * PADK + q * 8) * 2;
            cp16(dB + off, bh + gr);
            cp16(dB + 2u * 128 * PADK + off, blo + gr);
        }
        CP_COMMIT();
    }

    uint32_t abh = smem_to_u32(Ah);
    uint32_t abl = smem_to_u32(Al);

    for (int t = 0; t < 4; ++t) {
        __nv_bfloat16* cur = (t & 1) ? Bbuf1 : Bbuf0;
        if (t < 3) {
            __nv_bfloat16* nxt = (t & 1) ? Bbuf0 : Bbuf1;
            uint32_t dB = smem_to_u32(nxt);
            const uint4* bh = (const uint4*)g_BH;
            const uint4* blo = (const uint4*)g_BL;
            int jtn = jt0 + t + 1;
            for (int i = tid; i < 2048; i += 256) {
                int row = i >> 4, q = i & 15;
                size_t gr = (size_t)(jtn * 128 + row) * 16 + q;
                uint32_t off = (uint32_t)(row * PADK + q * 8) * 2;
                cp16(dB + off, bh + gr);
                cp16(dB + 2u * 128 * PADK + off, blo + gr);
            }
            CP_COMMIT();
            asm volatile("cp.async.wait_group 1;" ::: "memory");
        } else {
            asm volatile("cp.async.wait_group 0;" ::: "memory");
        }
        __syncthreads();

        uint32_t bhiA = smem_to_u32(cur);
        uint32_t bloA = smem_to_u32(cur + 2 * 64 * PADK);

        float c[2][8][4];
#pragma unroll
        for (int mi = 0; mi < 2; mi++)
#pragma unroll
            for (int q = 0; q < 8; q++)
#pragma unroll
                for (int v = 0; v < 4; v++) c[mi][q][v] = 0.f;

        uint32_t aR[2][2][4];
        uint32_t bR[2][8][2];

        // fragment loader for flattened iteration i (product = i/8, k0 = (i%8)*16)
#define LDFRAG(I, BUF) do {                                                      \
            int _p = (I) >> 3;                                                   \
            uint32_t _k2 = (uint32_t)(((I) & 7) << 5);                           \
            uint32_t _ab = (_p == 2) ? abl : abh;                                \
            uint32_t _bb = (_p == 1) ? bloA : bhiA;                              \
            _Pragma("unroll")                                                    \
            for (int mi = 0; mi < 2; mi++) {                                     \
                asm volatile("ldmatrix.sync.aligned.m8n8.x4.shared.b16 "        \
                    "{%0,%1,%2,%3}, [%4];"                                       \
                    : "=r"(aR[BUF][mi][0]), "=r"(aR[BUF][mi][1]),                \
                      "=r"(aR[BUF][mi][2]), "=r"(aR[BUF][mi][3])                 \
                    : "r"(_ab + aBase[mi] + _k2));                               \
            }                                                                    \
            _Pragma("unroll")                                                    \
            for (int q = 0; q < 4; q++) {                                        \
                uint32_t r0, r1, r2, r3;                                         \
                asm volatile("ldmatrix.sync.aligned.m8n8.x4.shared.b16 "        \
                    "{%0,%1,%2,%3}, [%4];"                                       \
                    : "=r"(r0), "=r"(r1), "=r"(r2), "=r"(r3)                     \
                    : "r"(_bb + bBase[q] + _k2));                                \
                bR[BUF][2 * q][0] = r0;     bR[BUF][2 * q][1] = r1;              \
                bR[BUF][2 * q + 1][0] = r2; bR[BUF][2 * q + 1][1] = r3;          \
            }                                                                    \
        } while (0)

        LDFRAG(0, 0);
#pragma unroll
        for (int i = 0; i < 24; i++) {
            int cb = i & 1, nb2 = (i + 1) & 1;
            if (i < 23) LDFRAG(i + 1, nb2);
#pragma unroll
            for (int mi = 0; mi < 2; mi++)
#pragma unroll
                for (int q = 0; q < 8; q++)
                    asm volatile(
                        "mma.sync.aligned.m16n8k16.row.col.f32.bf16.bf16.f32 "
                        "{%0,%1,%2,%3},{%4,%5,%6,%7},{%8,%9},{%0,%1,%2,%3};"
                        : "+f"(c[mi][q][0]), "+f"(c[mi][q][1]),
                          "+f"(c[mi][q][2]), "+f"(c[mi][q][3])
                        : "r"(aR[cb][mi][0]), "r"(aR[cb][mi][1]),
                          "r"(aR[cb][mi][2]), "r"(aR[cb][mi][3]),
                          "r"(bR[cb][q][0]), "r"(bR[cb][q][1]));
        }
#undef LDFRAG

        {
            int jt = jt0 + t;
            float* base; const float* bb; int colTile;
            if (jt < 16) { base = g_XL; bb = bl + jt * 128; colTile = jt * 128; }
            else { base = g_XR; bb = br + (jt - 16) * 128; colTile = (jt - 16) * 128; }
            int rrow = lane >> 2, cc2 = (lane & 3) * 2;
#pragma unroll
            for (int mi = 0; mi < 2; mi++) {
                int gm0 = m0 + wm + mi * 16 + rrow;
#pragma unroll
                for (int q = 0; q < 8; q++) {
                    int col = wn + q * 8 + cc2;
                    float b0v = bb[col], b1v = bb[col + 1];
                    if (gm0 < Nn) {
                        float2 v; v.x = c[mi][q][0] + b0v; v.y = c[mi][q][1] + b1v;
                        *(float2*)&base[(size_t)gm0 * 2048 + colTile + col] = v;
                    }
                    if (gm0 + 8 < Nn) {
                        float2 v; v.x = c[mi][q][2] + b0v; v.y = c[mi][q][3] + b1v;
                        *(float2*)&base[(size_t)(gm0 + 8) * 2048 + colTile + col] = v;
                    }
                }
            }
        }
        __syncthreads();
    }
}

// ---------------- edge bucketing by relation (warp-aggregated counting sort) ------
__global__ void hist_kernel(const int* __restrict__ et, int E) {
    int i = blockIdx.x * blockDim.x + threadIdx.x;
    if (i >= E) return;
    int r = et[i];
    unsigned act = __activemask();
    unsigned peers = __match_any_sync(act, r);
    int leader = __ffs(peers) - 1;
    if ((threadIdx.x & 31) == leader) atomicAdd(&g_CNT[r], __popc(peers));
}
__global__ void prefix_kernel() {
    if (threadIdx.x == 0) {
        int s = 0;
        for (int r = 0; r < R; r++) { g_BASE[r] = s; s += g_CNT[r]; }
        g_BASE[R] = s;
    }
}
__global__ void scatter_kernel(const int* __restrict__ et, int E) {
    int i = blockIdx.x * blockDim.x + threadIdx.x;
    if (i >= E) return;
    int lane = threadIdx.x & 31;
    int r = et[i];
    unsigned act = __activemask();
    unsigned peers = __match_any_sync(act, r);
    int leader = __ffs(peers) - 1;
    int rank = __popc(peers & ((1u << lane) - 1u));
    int base = 0;
    if (lane == leader) base = atomicAdd(&g_CUR[r], __popc(peers));
    base = __shfl_sync(act, base, leader);
    g_EPERM[g_BASE[r] + base + rank] = i;
}

// ---------------- edge scores + exp + denom (8 same-relation edges / block) -------
__global__ __launch_bounds__(128) void edge_score_kernel(
    const int* __restrict__ ei, const int* __restrict__ et,
    const float* __restrict__ ea, const float* __restrict__ rel,
    const float* __restrict__ We, const float* __restrict__ att, int E)
{
    int t = threadIdx.x;
    int e0 = blockIdx.x * 8;
    int ne = min(8, E - e0);
    __shared__ int s_e[8], s_src[8], s_dst[8], s_r[8];
    __shared__ float s_sw[8][DW];
    if (t < 8) {
        int k = g_EPERM[(t < ne) ? (e0 + t) : e0];
        s_e[t] = k; s_src[t] = ei[k]; s_dst[t] = ei[E + k]; s_r[t] = et[k];
    }
    __syncthreads();
    for (int i = t; i < 8 * DW; i += 128) {
        int j = i / DW, d = i % DW;
        s_sw[j][d] = (d < DE) ? ea[(size_t)s_e[j] * DE + d] : rel[s_r[j] * DR + (d - DE)];
    }
    __syncthreads();

    int hc = t * 4;
    int head = t >> 5;
    float4 w[DW];
    float4 a4 = make_float4(0.f, 0.f, 0.f, 0.f);
    int rcur = -1;

    for (int j = 0; j < ne; j++) {
        int r = s_r[j];
        if (r != rcur) {
            const float* Wp = We + (size_t)r * DW * HC + hc;
#pragma unroll
            for (int d = 0; d < DW; d++) w[d] = *(const float4*)&Wp[(size_t)d * HC];
            a4 = *(const float4*)&att[r * HC + hc];
            rcur = r;
        }
        float4 xl = __ldcg((const float4*)&g_XL[(size_t)s_src[j] * 2048 + r * 512 + hc]);
        float4 xr = __ldcg((const float4*)&g_XR[(size_t)s_dst[j] * 2048 + r * 512 + hc]);
        float4 ef = make_float4(0.f, 0.f, 0.f, 0.f);
#pragma unroll
        for (int d = 0; d < DW; d++) {
            float s = s_sw[j][d];
            ef.x += s * w[d].x; ef.y += s * w[d].y;
            ef.z += s * w[d].z; ef.w += s * w[d].w;
        }
        float p = 0.f, v;
        v = xl.x + xr.x + ef.x; v = v > 0.f ? v : 0.2f * v; p += v * a4.x;
        v = xl.y + xr.y + ef.y; v = v > 0.f ? v : 0.2f * v; p += v * a4.y;
        v = xl.z + xr.z + ef.z; v = v > 0.f ? v : 0.2f * v; p += v * a4.z;
        v = xl.w + xr.w + ef.w; v = v > 0.f ? v : 0.2f * v; p += v * a4.w;
#pragma unroll
        for (int o = 16; o; o >>= 1) p += __shfl_down_sync(0xffffffffu, p, o);
        if ((t & 31) == 0) {
            // scores are bounded (~|s|<10) -> exp without max subtraction is safe
            float ex = expf(p);
            g_EXPS[(size_t)s_e[j] * H + head] = ex;
            atomicAdd(&g_DENOM[((size_t)s_dst[j] * R + r) * H + head], ex);
        }
    }
}

// ---------------- normalize + scatter messages (head-mean folded in) ----------------
__global__ __launch_bounds__(128) void message_kernel(
    const int* __restrict__ ei, const int* __restrict__ et, int E)
{
    int w = threadIdx.x >> 5;
    int lane = threadIdx.x & 31;
    int e = blockIdx.x * 4 + w;
    if (e >= E) return;
    int src = ei[e], dst = ei[E + e], r = et[e];
    size_t segb = ((size_t)dst * R + r) * H;
    float al[4];
#pragma unroll
    for (int k = 0; k < 4; k++) al[k] = g_EXPS[(size_t)e * H + k] / g_DENOM[segb + k];
    int c = lane * 4;
    const float* xp = &g_XL[(size_t)src * 2048 + r * 512];
    float4 acc = make_float4(0.f, 0.f, 0.f, 0.f);
#pragma unroll
    for (int k = 0; k < 4; k++) {
        float4 x = __ldcg((const float4*)&xp[k * 128 + c]);
        acc.x += al[k] * x.x; acc.y += al[k] * x.y;
        acc.z += al[k] * x.z; acc.w += al[k] * x.w;
    }
    float* hb = &g_HREL[((size_t)dst * R + r) * 128 + c];
    atomicAdd(&hb[0], 0.25f * acc.x);
    atomicAdd(&hb[1], 0.25f * acc.y);
    atomicAdd(&hb[2], 0.25f * acc.z);
    atomicAdd(&hb[3], 0.25f * acc.w);
}

// ---------------- gated fusion + LN1 + FFN (f32x2) + LN2 : 32 nodes / block -------
#define H1T(f, n) smf[(f) * 34 + (n)]
#define UST(j, n) smf[128 * 34 + (j) * 34 + (n)]
#define PSN(n, c) smf[128 * 34 + 256 * 34 + (n) * 128 + (c)]
#define NODE_SMEM ((128 * 34 + 256 * 34 + 32 * 128) * 4)

__global__ __launch_bounds__(256, 2) void node_kernel(
    const float* __restrict__ hin, const float* __restrict__ bias, const float* __restrict__ gate,
    const float* __restrict__ g1, const float* __restrict__ bt1,
    const float* __restrict__ g2, const float* __restrict__ bt2,
    const float* __restrict__ Wf1, const float* __restrict__ bf1,
    const float* __restrict__ Wf2, const float* __restrict__ bf2,
    float* __restrict__ out, int N)
{
    extern __shared__ float smf[];
    int t = threadIdx.x, w = t >> 5, lane = t & 31;
    int nb = blockIdx.x * 32;

    float q0 = gate[0], q1 = gate[1], q2 = gate[2], q3 = gate[3];
    float gm = fmaxf(fmaxf(q0, q1), fmaxf(q2, q3));
    float e0 = expf(q0 - gm), e1 = expf(q1 - gm), e2 = expf(q2 - gm), e3 = expf(q3 - gm);
    float gs = e0 + e1 + e2 + e3;
    float gw0 = e0 / gs, gw1 = e1 / gs, gw2 = e2 / gs, gw3 = e3 / gs;

#pragma unroll
    for (int q = 0; q < 4; q++) {
        int ni = w * 4 + q;
        int n = nb + ni;
        bool valid = n < N;
        const float* hr = g_HREL + (size_t)n * 512;
        const float* hp = hin + (size_t)n * 128;
        float y[4];
        float s = 0.f, s2 = 0.f;
#pragma unroll
        for (int k = 0; k < 4; k++) {
            int c = k * 32 + lane;
            float v = 0.f;
            if (valid) {
                float hm = gw0 * (hr[c] + bias[c])
                         + gw1 * (hr[128 + c] + bias[128 + c])
                         + gw2 * (hr[256 + c] + bias[256 + c])
                         + gw3 * (hr[384 + c] + bias[384 + c]);
                v = hp[c] + hm;
            }
            y[k] = v; s += v; s2 += v * v;
        }
#pragma unroll
        for (int o = 16; o; o >>= 1) {
            s += __shfl_xor_sync(0xffffffffu, s, o);
            s2 += __shfl_xor_sync(0xffffffffu, s2, o);
        }
        float m = s * (1.f / 128.f);
        float rs = rsqrtf(s2 * (1.f / 128.f) - m * m + 1e-5f);
#pragma unroll
        for (int k = 0; k < 4; k++) {
            int c = k * 32 + lane;
            H1T(c, ni) = (y[k] - m) * rs * g1[c] + bt1[c];
        }
    }
    __syncthreads();

    {
        unsigned long long acc[16];
#pragma unroll
        for (int p = 0; p < 16; p++) acc[p] = 0ull;
        for (int f = 0; f < 128; f++) {
            float wv = Wf1[f * FFNW + t];
            unsigned long long wp;
            asm("mov.b64 %0, {%1, %1};" : "=l"(wp) : "f"(wv));
#pragma unroll
            for (int p = 0; p < 16; p++) {
                unsigned long long hp = *(const unsigned long long*)&H1T(f, 2 * p);
                asm("fma.rn.f32x2 %0, %1, %2, %0;" : "+l"(acc[p]) : "l"(hp), "l"(wp));
            }
        }
        float bj = bf1[t];
#pragma unroll
        for (int p = 0; p < 16; p++) {
            float u0, u1;
            asm("mov.b64 {%0, %1}, %2;" : "=f"(u0), "=f"(u1) : "l"(acc[p]));
            u0 += bj; u1 += bj;
            UST(t, 2 * p) = u0 / (1.f + expf(-u0));
            UST(t, 2 * p + 1) = u1 / (1.f + expf(-u1));
        }
    }
    __syncthreads();

    {
        int c = t & 127, half = t >> 7;
        unsigned long long acc[16];
#pragma unroll
        for (int p = 0; p < 16; p++) acc[p] = 0ull;
        for (int jj = 0; jj < 128; jj++) {
            int j = half * 128 + jj;
            float wv = Wf2[j * 128 + c];
            unsigned long long wp;
            asm("mov.b64 %0, {%1, %1};" : "=l"(wp) : "f"(wv));
#pragma unroll
            for (int p = 0; p < 16; p++) {
                unsigned long long up = *(const unsigned long long*)&UST(j, 2 * p);
                asm("fma.rn.f32x2 %0, %1, %2, %0;" : "+l"(acc[p]) : "l"(up), "l"(wp));
            }
        }
        if (half == 0) {
#pragma unroll
            for (int p = 0; p < 16; p++) {
                float v0, v1;
                asm("mov.b64 {%0, %1}, %2;" : "=f"(v0), "=f"(v1) : "l"(acc[p]));
                PSN(2 * p, c) = v0;
                PSN(2 * p + 1, c) = v1;
            }
        }
        __syncthreads();
        if (half == 1) {
            float bc = bf2[c];
#pragma unroll
            for (int p = 0; p < 16; p++) {
                float v0, v1;
                asm("mov.b64 {%0, %1}, %2;" : "=f"(v0), "=f"(v1) : "l"(acc[p]));
                PSN(2 * p, c) += v0 + bc + H1T(c, 2 * p);
                PSN(2 * p + 1, c) += v1 + bc + H1T(c, 2 * p + 1);
            }
        }
    }
    __syncthreads();

#pragma unroll
    for (int q = 0; q < 4; q++) {
        int ni = w * 4 + q;
        int n = nb + ni;
        float v[4];
        float s = 0.f, s2 = 0.f;
#pragma unroll
        for (int k = 0; k < 4; k++) {
            int c = k * 32 + lane;
            float x = PSN(ni, c);
            v[k] = x; s += x; s2 += x * x;
        }
#pragma unroll
        for (int o = 16; o; o >>= 1) {
            s += __shfl_xor_sync(0xffffffffu, s, o);
            s2 += __shfl_xor_sync(0xffffffffu, s2, o);
        }
        float m = s * (1.f / 128.f);
        float rs = rsqrtf(s2 * (1.f / 128.f) - m * m + 1e-5f);
        if (n < N) {
#pragma unroll
            for (int k = 0; k < 4; k++) {
                int c = k * 32 + lane;
                out[(size_t)n * 128 + c] = (v[k] - m) * rs * g2[c] + bt2[c];
            }
        }
    }
}

// ---------------- launcher ----------------
extern "C" void kernel_launch(void* const* d_in, const int* in_sizes, int n_in,
                              void* d_out, int out_size)
{
    const float* h    = (const float*)d_in[0];
    const int*   ei   = (const int*)d_in[1];
    const float* ea   = (const float*)d_in[2];
    const int*   et   = (const int*)d_in[3];
    const float* rel  = (const float*)d_in[4];
    const float* Wl   = (const float*)d_in[5];
    const float* bl   = (const float*)d_in[6];
    const float* Wr   = (const float*)d_in[7];
    const float* br   = (const float*)d_in[8];
    const float* We   = (const float*)d_in[9];
    const float* att  = (const float*)d_in[10];
    const float* bias = (const float*)d_in[11];
    const float* gate = (const float*)d_in[12];
    const float* g1   = (const float*)d_in[13];
    const float* bt1  = (const float*)d_in[14];
    const float* g2   = (const float*)d_in[15];
    const float* bt2  = (const float*)d_in[16];
    const float* Wf1  = (const float*)d_in[17];
    const float* bf1  = (const float*)d_in[18];
    const float* Wf2  = (const float*)d_in[19];
    const float* bf2  = (const float*)d_in[20];

    int N = in_sizes[0] / F;
    int E = in_sizes[3];
    float* out = (float*)d_out;

    const int SMEM_GEMM = 6 * 128 * PADK * 2;  // 208896 bytes
    cudaFuncSetAttribute(proj_hmma_kernel, cudaFuncAttributeMaxDynamicSharedMemorySize, SMEM_GEMM);
    cudaFuncSetAttribute(node_kernel, cudaFuncAttributeMaxDynamicSharedMemorySize, NODE_SMEM);

    // order: proj is the 4th launch so the profiler slot captures it
    prep_a_kernel<<<(N * F + 255) / 256, 256>>>(h, N);
    prep_w_kernel<<<(NCOL * F + 255) / 256, 256>>>(Wl, Wr);
    init_kernel<<<4096, 256>>>(N);

    dim3 gg((N + 127) / 128, 8);
    proj_hmma_kernel<<<gg, 256, SMEM_GEMM>>>(bl, br, N);

    hist_kernel<<<(E + 255) / 256, 256>>>(et, E);
    prefix_kernel<<<1, 32>>>();
    scatter_kernel<<<(E + 255) / 256, 256>>>(et, E);

    edge_score_kernel<<<(E + 7) / 8, 128>>>(ei, et, ea, rel, We, att, E);
    message_kernel<<<(E + 3) / 4, 128>>>(ei, et, E);

    node_kernel<<<(N + 31) / 32, 256, NODE_SMEM>>>(h, bias, gate, g1, bt1, g2, bt2,
                                                   Wf1, bf1, Wf2, bf2, out, N);
}

// round 14
// speedup vs baseline: 1.1467x; 1.0496x over previous
#include <cuda_runtime.h>
#include <cuda_bf16.h>
#include <math.h>
#include <stdint.h>

#define F    128
#define R    4
#define H    4
#define HC   512
#define DE   16
#define DR   8
#define DW   24   // De + Dr
#define FFNW 256
#define MAXN 40000
#define MAXE 150000
#define NCOL 4096  // 2 * R * HC  (XL cols 0..2047, XR cols 2048..4095)
#define PADK 136   // padded bf16 row length in smem

// ---------------- scratch (static device memory; no allocs allowed) ----------------
__device__ float g_XL[(size_t)MAXN * 2048];
__device__ float g_XR[(size_t)MAXN * 2048];
__device__ float g_HREL[(size_t)MAXN * R * 128];
__device__ float g_EXPS[(size_t)MAXE * H];
__device__ float g_DENOM[(size_t)MAXN * R * H];
__device__ __nv_bfloat16 g_AH[(size_t)MAXN * F];
__device__ __nv_bfloat16 g_AL[(size_t)MAXN * F];
__device__ __nv_bfloat16 g_BH[(size_t)NCOL * F];   // transposed weights [ncol][k]
__device__ __nv_bfloat16 g_BL[(size_t)NCOL * F];
__device__ int g_CNT[R];
__device__ int g_BASE[R + 1];
__device__ int g_CUR[R];
__device__ int g_EPERM[MAXE];

__device__ __forceinline__ uint32_t smem_to_u32(const void* p) {
    uint32_t a;
    asm("{ .reg .u64 t; cvta.to.shared.u64 t, %1; cvt.u32.u64 %0, t; }" : "=r"(a) : "l"(p));
    return a;
}
__device__ __forceinline__ void cp16(uint32_t dst, const void* src) {
    asm volatile("cp.async.cg.shared.global [%0], [%1], 16;" :: "r"(dst), "l"(src));
}
__device__ __forceinline__ void cp16z(uint32_t dst, const void* src, int sz) {
    asm volatile("cp.async.cg.shared.global [%0], [%1], 16, %2;" :: "r"(dst), "l"(src), "r"(sz));
}
#define CP_COMMIT() asm volatile("cp.async.commit_group;" ::: "memory")

// ---------------- prep: fp32 -> bf16 hi/lo split ----------------
__global__ void prep_a_kernel(const float* __restrict__ h, int Nn) {
    int i = blockIdx.x * blockDim.x + threadIdx.x;
    if (i >= Nn * F) return;
    float v = h[i];
    __nv_bfloat16 hi = __float2bfloat16(v);
    g_AH[i] = hi;
    g_AL[i] = __float2bfloat16(v - __bfloat162float(hi));
}
__global__ void prep_w_kernel(const float* __restrict__ Wl, const float* __restrict__ Wr) {
    int i = blockIdx.x * blockDim.x + threadIdx.x;
    if (i >= NCOL * F) return;
    int j = i >> 7, k = i & 127;
    float w;
    if (j < 2048) w = Wl[(size_t)((j >> 9) * F + k) * HC + (j & 511)];
    else { int j2 = j - 2048; w = Wr[(size_t)((j2 >> 9) * F + k) * HC + (j2 & 511)]; }
    __nv_bfloat16 hi = __float2bfloat16(w);
    g_BH[i] = hi;
    g_BL[i] = __float2bfloat16(w - __bfloat162float(hi));
}

// ---------------- init ----------------
__global__ void init_kernel(int N) {
    if (blockIdx.x == 0 && threadIdx.x < R) { g_CNT[threadIdx.x] = 0; g_CUR[threadIdx.x] = 0; }
    size_t total4 = (size_t)N * R * 32;   // HREL as float4
    size_t small = (size_t)N * R * H;
    float4 z = make_float4(0.f, 0.f, 0.f, 0.f);
    for (size_t i = (size_t)blockIdx.x * blockDim.x + threadIdx.x; i < total4;
         i += (size_t)gridDim.x * blockDim.x) {
        ((float4*)g_HREL)[i] = z;
        if (i < small) g_DENOM[i] = 0.f;
    }
}

// ---------------- projection GEMM via mma.sync bf16 (hi/lo split, fp32 acc) ------
// 256 threads / 8 warps, 4x2 warp grid, warp tile 32m x 64n. C tile 128x128.
// Fragments (Ah, Al, Bh, Bl) loaded ONCE per k-step; 48 MMAs issued against them
// (products hi*hi + hi*lo + lo*hi share operands) -> smem bytes/MAC = 0.0625,
// balanced with the HMMA pipe.
__global__ __launch_bounds__(256, 1) void proj_hmma_kernel(
    const float* __restrict__ bl, const float* __restrict__ br, int Nn)
{
    extern __shared__ char smem[];
    __nv_bfloat16* Ah = (__nv_bfloat16*)smem;          // [128][PADK]
    __nv_bfloat16* Al = Ah + 128 * PADK;
    __nv_bfloat16* Bbuf0 = Al + 128 * PADK;            // hi then lo, 2*128*PADK
    __nv_bfloat16* Bbuf1 = Bbuf0 + 2 * 128 * PADK;

    int tid = threadIdx.x, wid = tid >> 5, lane = tid & 31;
    int m0 = blockIdx.x * 128;
    int jt0 = blockIdx.y * 4;
    int wm = (wid & 3) * 32;
    int wn = (wid >> 2) * 64;
    int g = lane >> 3, rr8 = lane & 7;

    // per-warp ldmatrix address bases (byte offsets within a tile)
    uint32_t aBase[2], bBase[4];
#pragma unroll
    for (int mi = 0; mi < 2; mi++)
        aBase[mi] = (uint32_t)(((wm + mi * 16 + (g & 1) * 8 + rr8) * PADK + (g >> 1) * 8) * 2);
#pragma unroll
    for (int q = 0; q < 4; q++)
        bBase[q] = (uint32_t)(((wn + q * 16 + (g >> 1) * 8 + rr8) * PADK + (g & 1) * 8) * 2);

    {
        uint32_t dA = smem_to_u32(Ah);
        uint32_t dAl = smem_to_u32(Al);
        const uint4* ah = (const uint4*)g_AH;
        const uint4* al = (const uint4*)g_AL;
        for (int i = tid; i < 2048; i += 256) {
            int row = i >> 4, q = i & 15;
            int gm = m0 + row;
            int sz = (gm < Nn) ? 16 : 0;
            size_t gi = (size_t)((gm < Nn) ? gm : 0) * 16 + q;
            uint32_t off = (uint32_t)(row * PADK + q * 8) * 2;
            cp16z(dA + off, ah + gi, sz);
            cp16z(dAl + off, al + gi, sz);
        }
        uint32_t dB = smem_to_u32(Bbuf0);
        const uint4* bh = (const uint4*)g_BH;
        const uint4* blo = (const uint4*)g_BL;
        for (int i = tid; i < 2048; i += 256) {
            int row = i >> 4, q = i & 15;
            size_t gr = (size_t)(jt0 * 128 + row) * 16 + q;
            uint32_t off = (uint32_t)(row * PADK + q * 8) * 2;
            cp16(dB + off, bh + gr);
            cp16(dB + 2u * 128 * PADK + off, blo + gr);
        }
        CP_COMMIT();
    }

    uint32_t abh = smem_to_u32(Ah);
    uint32_t abl = smem_to_u32(Al);

    for (int t = 0; t < 4; ++t) {
        __nv_bfloat16* cur = (t & 1) ? Bbuf1 : Bbuf0;
        if (t < 3) {
            __nv_bfloat16* nxt = (t & 1) ? Bbuf0 : Bbuf1;
            uint32_t dB = smem_to_u32(nxt);
            const uint4* bh = (const uint4*)g_BH;
            const uint4* blo = (const uint4*)g_BL;
            int jtn = jt0 + t + 1;
            for (int i = tid; i < 2048; i += 256) {
                int row = i >> 4, q = i & 15;
                size_t gr = (size_t)(jtn * 128 + row) * 16 + q;
                uint32_t off = (uint32_t)(row * PADK + q * 8) * 2;
                cp16(dB + off, bh + gr);
                cp16(dB + 2u * 128 * PADK + off, blo + gr);
            }
            CP_COMMIT();
            asm volatile("cp.async.wait_group 1;" ::: "memory");
        } else {
            asm volatile("cp.async.wait_group 0;" ::: "memory");
        }
        __syncthreads();

        uint32_t bhiA = smem_to_u32(cur);
        uint32_t bloA = smem_to_u32(cur + 2 * 64 * PADK);

        float c[2][8][4];
#pragma unroll
        for (int mi = 0; mi < 2; mi++)
#pragma unroll
            for (int q = 0; q < 8; q++)
#pragma unroll
                for (int v = 0; v < 4; v++) c[mi][q][v] = 0.f;

#pragma unroll
        for (int k0 = 0; k0 < 128; k0 += 16) {
            uint32_t k2 = (uint32_t)(k0 * 2);
            uint32_t ah[2][4], al[2][4], bh[8][2], bo[8][2];
            // A hi/lo fragments: 4 LDSM
#pragma unroll
            for (int mi = 0; mi < 2; mi++) {
                asm volatile("ldmatrix.sync.aligned.m8n8.x4.shared.b16 {%0,%1,%2,%3}, [%4];"
                    : "=r"(ah[mi][0]), "=r"(ah[mi][1]), "=r"(ah[mi][2]), "=r"(ah[mi][3])
                    : "r"(abh + aBase[mi] + k2));
                asm volatile("ldmatrix.sync.aligned.m8n8.x4.shared.b16 {%0,%1,%2,%3}, [%4];"
                    : "=r"(al[mi][0]), "=r"(al[mi][1]), "=r"(al[mi][2]), "=r"(al[mi][3])
                    : "r"(abl + aBase[mi] + k2));
            }
            // B hi/lo fragments: 8 LDSM
#pragma unroll
            for (int q = 0; q < 4; q++) {
                uint32_t r0, r1, r2, r3;
                asm volatile("ldmatrix.sync.aligned.m8n8.x4.shared.b16 {%0,%1,%2,%3}, [%4];"
                    : "=r"(r0), "=r"(r1), "=r"(r2), "=r"(r3)
                    : "r"(bhiA + bBase[q] + k2));
                bh[2 * q][0] = r0;     bh[2 * q][1] = r1;
                bh[2 * q + 1][0] = r2; bh[2 * q + 1][1] = r3;
                asm volatile("ldmatrix.sync.aligned.m8n8.x4.shared.b16 {%0,%1,%2,%3}, [%4];"
                    : "=r"(r0), "=r"(r1), "=r"(r2), "=r"(r3)
                    : "r"(bloA + bBase[q] + k2));
                bo[2 * q][0] = r0;     bo[2 * q][1] = r1;
                bo[2 * q + 1][0] = r2; bo[2 * q + 1][1] = r3;
            }
            // 48 MMAs: Ah*Bh, Ah*Bl, Al*Bh all accumulate into c
#define MMA16(AR, BR)                                                            \
            _Pragma("unroll")                                                    \
            for (int mi = 0; mi < 2; mi++)                                       \
                _Pragma("unroll")                                                \
                for (int q = 0; q < 8; q++)                                      \
                    asm volatile(                                                \
                        "mma.sync.aligned.m16n8k16.row.col.f32.bf16.bf16.f32 "  \
                        "{%0,%1,%2,%3},{%4,%5,%6,%7},{%8,%9},{%0,%1,%2,%3};"     \
                        : "+f"(c[mi][q][0]), "+f"(c[mi][q][1]),                  \
                          "+f"(c[mi][q][2]), "+f"(c[mi][q][3])                   \
                        : "r"(AR[mi][0]), "r"(AR[mi][1]),                        \
                          "r"(AR[mi][2]), "r"(AR[mi][3]),                        \
                          "r"(BR[q][0]), "r"(BR[q][1]))
            MMA16(ah, bh);
            MMA16(ah, bo);
            MMA16(al, bh);
#undef MMA16
        }

        {
            int jt = jt0 + t;
            float* base; const float* bb; int colTile;
            if (jt < 16) { base = g_XL; bb = bl + jt * 128; colTile = jt * 128; }
            else { base = g_XR; bb = br + (jt - 16) * 128; colTile = (jt - 16) * 128; }
            int rrow = lane >> 2, cc2 = (lane & 3) * 2;
#pragma unroll
            for (int mi = 0; mi < 2; mi++) {
                int gm0 = m0 + wm + mi * 16 + rrow;
#pragma unroll
                for (int q = 0; q < 8; q++) {
                    int col = wn + q * 8 + cc2;
                    float b0v = bb[col], b1v = bb[col + 1];
                    if (gm0 < Nn) {
                        float2 v; v.x = c[mi][q][0] + b0v; v.y = c[mi][q][1] + b1v;
                        *(float2*)&base[(size_t)gm0 * 2048 + colTile + col] = v;
                    }
                    if (gm0 + 8 < Nn) {
                        float2 v; v.x = c[mi][q][2] + b0v; v.y = c[mi][q][3] + b1v;
                        *(float2*)&base[(size_t)(gm0 + 8) * 2048 + colTile + col] = v;
                    }
                }
            }
        }
        __syncthreads();
    }
}

// ---------------- edge bucketing by relation (warp-aggregated counting sort) ------
__global__ void hist_kernel(const int* __restrict__ et, int E) {
    int i = blockIdx.x * blockDim.x + threadIdx.x;
    if (i >= E) return;
    int r = et[i];
    unsigned act = __activemask();
    unsigned peers = __match_any_sync(act, r);
    int leader = __ffs(peers) - 1;
    if ((threadIdx.x & 31) == leader) atomicAdd(&g_CNT[r], __popc(peers));
}
__global__ void prefix_kernel() {
    if (threadIdx.x == 0) {
        int s = 0;
        for (int r = 0; r < R; r++) { g_BASE[r] = s; s += g_CNT[r]; }
        g_BASE[R] = s;
    }
}
__global__ void scatter_kernel(const int* __restrict__ et, int E) {
    int i = blockIdx.x * blockDim.x + threadIdx.x;
    if (i >= E) return;
    int lane = threadIdx.x & 31;
    int r = et[i];
    unsigned act = __activemask();
    unsigned peers = __match_any_sync(act, r);
    int leader = __ffs(peers) - 1;
    int rank = __popc(peers & ((1u << lane) - 1u));
    int base = 0;
    if (lane == leader) base = atomicAdd(&g_CUR[r], __popc(peers));
    base = __shfl_sync(act, base, leader);
    g_EPERM[g_BASE[r] + base + rank] = i;
}

// ---------------- edge scores + exp + denom (8 same-relation edges / block) -------
__global__ __launch_bounds__(128) void edge_score_kernel(
    const int* __restrict__ ei, const int* __restrict__ et,
    const float* __restrict__ ea, const float* __restrict__ rel,
    const float* __restrict__ We, const float* __restrict__ att, int E)
{
    int t = threadIdx.x;
    int e0 = blockIdx.x * 8;
    int ne = min(8, E - e0);
    __shared__ int s_e[8], s_src[8], s_dst[8], s_r[8];
    __shared__ float s_sw[8][DW];
    if (t < 8) {
        int k = g_EPERM[(t < ne) ? (e0 + t) : e0];
        s_e[t] = k; s_src[t] = ei[k]; s_dst[t] = ei[E + k]; s_r[t] = et[k];
    }
    __syncthreads();
    for (int i = t; i < 8 * DW; i += 128) {
        int j = i / DW, d = i % DW;
        s_sw[j][d] = (d < DE) ? ea[(size_t)s_e[j] * DE + d] : rel[s_r[j] * DR + (d - DE)];
    }
    __syncthreads();

    int hc = t * 4;
    int head = t >> 5;
    float4 w[DW];
    float4 a4 = make_float4(0.f, 0.f, 0.f, 0.f);
    int rcur = -1;

    for (int j = 0; j < ne; j++) {
        int r = s_r[j];
        if (r != rcur) {
            const float* Wp = We + (size_t)r * DW * HC + hc;
#pragma unroll
            for (int d = 0; d < DW; d++) w[d] = *(const float4*)&Wp[(size_t)d * HC];
            a4 = *(const float4*)&att[r * HC + hc];
            rcur = r;
        }
        float4 xl = __ldcg((const float4*)&g_XL[(size_t)s_src[j] * 2048 + r * 512 + hc]);
        float4 xr = __ldcg((const float4*)&g_XR[(size_t)s_dst[j] * 2048 + r * 512 + hc]);
        float4 ef = make_float4(0.f, 0.f, 0.f, 0.f);
#pragma unroll
        for (int d = 0; d < DW; d++) {
            float s = s_sw[j][d];
            ef.x += s * w[d].x; ef.y += s * w[d].y;
            ef.z += s * w[d].z; ef.w += s * w[d].w;
        }
        float p = 0.f, v;
        v = xl.x + xr.x + ef.x; v = v > 0.f ? v : 0.2f * v; p += v * a4.x;
        v = xl.y + xr.y + ef.y; v = v > 0.f ? v : 0.2f * v; p += v * a4.y;
        v = xl.z + xr.z + ef.z; v = v > 0.f ? v : 0.2f * v; p += v * a4.z;
        v = xl.w + xr.w + ef.w; v = v > 0.f ? v : 0.2f * v; p += v * a4.w;
#pragma unroll
        for (int o = 16; o; o >>= 1) p += __shfl_down_sync(0xffffffffu, p, o);
        if ((t & 31) == 0) {
            // scores are bounded (~|s|<10) -> exp without max subtraction is safe
            float ex = expf(p);
            g_EXPS[(size_t)s_e[j] * H + head] = ex;
            atomicAdd(&g_DENOM[((size_t)s_dst[j] * R + r) * H + head], ex);
        }
    }
}

// ---------------- normalize + scatter messages (head-mean folded in) ----------------
__global__ __launch_bounds__(128) void message_kernel(
    const int* __restrict__ ei, const int* __restrict__ et, int E)
{
    int w = threadIdx.x >> 5;
    int lane = threadIdx.x & 31;
    int e = blockIdx.x * 4 + w;
    if (e >= E) return;
    int src = ei[e], dst = ei[E + e], r = et[e];
    size_t segb = ((size_t)dst * R + r) * H;
    float al[4];
#pragma unroll
    for (int k = 0; k < 4; k++) al[k] = g_EXPS[(size_t)e * H + k] / g_DENOM[segb + k];
    int c = lane * 4;
    const float* xp = &g_XL[(size_t)src * 2048 + r * 512];
    float4 acc = make_float4(0.f, 0.f, 0.f, 0.f);
#pragma unroll
    for (int k = 0; k < 4; k++) {
        float4 x = __ldcg((const float4*)&xp[k * 128 + c]);
        acc.x += al[k] * x.x; acc.y += al[k] * x.y;
        acc.z += al[k] * x.z; acc.w += al[k] * x.w;
    }
    float* hb = &g_HREL[((size_t)dst * R + r) * 128 + c];
    atomicAdd(&hb[0], 0.25f * acc.x);
    atomicAdd(&hb[1], 0.25f * acc.y);
    atomicAdd(&hb[2], 0.25f * acc.z);
    atomicAdd(&hb[3], 0.25f * acc.w);
}

// ---------------- gated fusion + LN1 + FFN (f32x2) + LN2 : 32 nodes / block -------
#define H1T(f, n) smf[(f) * 34 + (n)]
#define UST(j, n) smf[128 * 34 + (j) * 34 + (n)]
#define PSN(n, c) smf[128 * 34 + 256 * 34 + (n) * 128 + (c)]
#define NODE_SMEM ((128 * 34 + 256 * 34 + 32 * 128) * 4)

__global__ __launch_bounds__(256, 2) void node_kernel(
    const float* __restrict__ hin, const float* __restrict__ bias, const float* __restrict__ gate,
    const float* __restrict__ g1, const float* __restrict__ bt1,
    const float* __restrict__ g2, const float* __restrict__ bt2,
    const float* __restrict__ Wf1, const float* __restrict__ bf1,
    const float* __restrict__ Wf2, const float* __restrict__ bf2,
    float* __restrict__ out, int N)
{
    extern __shared__ float smf[];
    int t = threadIdx.x, w = t >> 5, lane = t & 31;
    int nb = blockIdx.x * 32;

    float q0 = gate[0], q1 = gate[1], q2 = gate[2], q3 = gate[3];
    float gm = fmaxf(fmaxf(q0, q1), fmaxf(q2, q3));
    float e0 = expf(q0 - gm), e1 = expf(q1 - gm), e2 = expf(q2 - gm), e3 = expf(q3 - gm);
    float gs = e0 + e1 + e2 + e3;
    float gw0 = e0 / gs, gw1 = e1 / gs, gw2 = e2 / gs, gw3 = e3 / gs;

#pragma unroll
    for (int q = 0; q < 4; q++) {
        int ni = w * 4 + q;
        int n = nb + ni;
        bool valid = n < N;
        const float* hr = g_HREL + (size_t)n * 512;
        const float* hp = hin + (size_t)n * 128;
        float y[4];
        float s = 0.f, s2 = 0.f;
#pragma unroll
        for (int k = 0; k < 4; k++) {
            int c = k * 32 + lane;
            float v = 0.f;
            if (valid) {
                float hm = gw0 * (hr[c] + bias[c])
                         + gw1 * (hr[128 + c] + bias[128 + c])
                         + gw2 * (hr[256 + c] + bias[256 + c])
                         + gw3 * (hr[384 + c] + bias[384 + c]);
                v = hp[c] + hm;
            }
            y[k] = v; s += v; s2 += v * v;
        }
#pragma unroll
        for (int o = 16; o; o >>= 1) {
            s += __shfl_xor_sync(0xffffffffu, s, o);
            s2 += __shfl_xor_sync(0xffffffffu, s2, o);
        }
        float m = s * (1.f / 128.f);
        float rs = rsqrtf(s2 * (1.f / 128.f) - m * m + 1e-5f);
#pragma unroll
        for (int k = 0; k < 4; k++) {
            int c = k * 32 + lane;
            H1T(c, ni) = (y[k] - m) * rs * g1[c] + bt1[c];
        }
    }
    __syncthreads();

    {
        unsigned long long acc[16];
#pragma unroll
        for (int p = 0; p < 16; p++) acc[p] = 0ull;
        for (int f = 0; f < 128; f++) {
            float wv = Wf1[f * FFNW + t];
            unsigned long long wp;
            asm("mov.b64 %0, {%1, %1};" : "=l"(wp) : "f"(wv));
#pragma unroll
            for (int p = 0; p < 16; p++) {
                unsigned long long hp = *(const unsigned long long*)&H1T(f, 2 * p);
                asm("fma.rn.f32x2 %0, %1, %2, %0;" : "+l"(acc[p]) : "l"(hp), "l"(wp));
            }
        }
        float bj = bf1[t];
#pragma unroll
        for (int p = 0; p < 16; p++) {
            float u0, u1;
            asm("mov.b64 {%0, %1}, %2;" : "=f"(u0), "=f"(u1) : "l"(acc[p]));
            u0 += bj; u1 += bj;
            UST(t, 2 * p) = u0 / (1.f + expf(-u0));
            UST(t, 2 * p + 1) = u1 / (1.f + expf(-u1));
        }
    }
    __syncthreads();

    {
        int c = t & 127, half = t >> 7;
        unsigned long long acc[16];
#pragma unroll
        for (int p = 0; p < 16; p++) acc[p] = 0ull;
        for (int jj = 0; jj < 128; jj++) {
            int j = half * 128 + jj;
            float wv = Wf2[j * 128 + c];
            unsigned long long wp;
            asm("mov.b64 %0, {%1, %1};" : "=l"(wp) : "f"(wv));
#pragma unroll
            for (int p = 0; p < 16; p++) {
                unsigned long long up = *(const unsigned long long*)&UST(j, 2 * p);
                asm("fma.rn.f32x2 %0, %1, %2, %0;" : "+l"(acc[p]) : "l"(up), "l"(wp));
            }
        }
        if (half == 0) {
#pragma unroll
            for (int p = 0; p < 16; p++) {
                float v0, v1;
                asm("mov.b64 {%0, %1}, %2;" : "=f"(v0), "=f"(v1) : "l"(acc[p]));
                PSN(2 * p, c) = v0;
                PSN(2 * p + 1, c) = v1;
            }
        }
        __syncthreads();
        if (half == 1) {
            float bc = bf2[c];
#pragma unroll
            for (int p = 0; p < 16; p++) {
                float v0, v1;
                asm("mov.b64 {%0, %1}, %2;" : "=f"(v0), "=f"(v1) : "l"(acc[p]));
                PSN(2 * p, c) += v0 + bc + H1T(c, 2 * p);
                PSN(2 * p + 1, c) += v1 + bc + H1T(c, 2 * p + 1);
            }
        }
    }
    __syncthreads();

#pragma unroll
    for (int q = 0; q < 4; q++) {
        int ni = w * 4 + q;
        int n = nb + ni;
        float v[4];
        float s = 0.f, s2 = 0.f;
#pragma unroll
        for (int k = 0; k < 4; k++) {
            int c = k * 32 + lane;
            float x = PSN(ni, c);
            v[k] = x; s += x; s2 += x * x;
        }
#pragma unroll
        for (int o = 16; o; o >>= 1) {
            s += __shfl_xor_sync(0xffffffffu, s, o);
            s2 += __shfl_xor_sync(0xffffffffu, s2, o);
        }
        float m = s * (1.f / 128.f);
        float rs = rsqrtf(s2 * (1.f / 128.f) - m * m + 1e-5f);
        if (n < N) {
#pragma unroll
            for (int k = 0; k < 4; k++) {
                int c = k * 32 + lane;
                out[(size_t)n * 128 + c] = (v[k] - m) * rs * g2[c] + bt2[c];
            }
        }
    }
}

// ---------------- launcher ----------------
extern "C" void kernel_launch(void* const* d_in, const int* in_sizes, int n_in,
                              void* d_out, int out_size)
{
    const float* h    = (const float*)d_in[0];
    const int*   ei   = (const int*)d_in[1];
    const float* ea   = (const float*)d_in[2];
    const int*   et   = (const int*)d_in[3];
    const float* rel  = (const float*)d_in[4];
    const float* Wl   = (const float*)d_in[5];
    const float* bl   = (const float*)d_in[6];
    const float* Wr   = (const float*)d_in[7];
    const float* br   = (const float*)d_in[8];
    const float* We   = (const float*)d_in[9];
    const float* att  = (const float*)d_in[10];
    const float* bias = (const float*)d_in[11];
    const float* gate = (const float*)d_in[12];
    const float* g1   = (const float*)d_in[13];
    const float* bt1  = (const float*)d_in[14];
    const float* g2   = (const float*)d_in[15];
    const float* bt2  = (const float*)d_in[16];
    const float* Wf1  = (const float*)d_in[17];
    const float* bf1  = (const float*)d_in[18];
    const float* Wf2  = (const float*)d_in[19];
    const float* bf2  = (const float*)d_in[20];

    int N = in_sizes[0] / F;
    int E = in_sizes[3];
    float* out = (float*)d_out;

    const int SMEM_GEMM = 6 * 128 * PADK * 2;  // 208896 bytes
    cudaFuncSetAttribute(proj_hmma_kernel, cudaFuncAttributeMaxDynamicSharedMemorySize, SMEM_GEMM);
    cudaFuncSetAttribute(node_kernel, cudaFuncAttributeMaxDynamicSharedMemorySize, NODE_SMEM);

    // order: proj is the 4th launch so the profiler slot captures it
    prep_a_kernel<<<(N * F + 255) / 256, 256>>>(h, N);
    prep_w_kernel<<<(NCOL * F + 255) / 256, 256>>>(Wl, Wr);
    init_kernel<<<4096, 256>>>(N);

    dim3 gg((N + 127) / 128, 8);
    proj_hmma_kernel<<<gg, 256, SMEM_GEMM>>>(bl, br, N);

    hist_kernel<<<(E + 255) / 256, 256>>>(et, E);
    prefix_kernel<<<1, 32>>>();
    scatter_kernel<<<(E + 255) / 256, 256>>>(et, E);

    edge_score_kernel<<<(E + 7) / 8, 128>>>(ei, et, ea, rel, We, att, E);
    message_kernel<<<(E + 3) / 4, 128>>>(ei, et, E);

    node_kernel<<<(N + 31) / 32, 256, NODE_SMEM>>>(h, bias, gate, g1, bt1, g2, bt2,
                                                   Wf1, bf1, Wf2, bf2, out, N);
}